// round 2
// baseline (speedup 1.0000x reference)
#include <cuda_runtime.h>
#include <cstdint>

// ---------------------------------------------------------------------------
// VGG-small 1w1a forward, batch 256.
// conv0 fp32 (XLA/Eigen-matching fma order) -> bn -> [bconv->(pool)->bn->ht]x5 -> fc
// Binary convs: channel-bitpacked XNOR+popcount (bit-exact even integers).
// All BN stats in fp64; all sign thresholds evaluated in fp64.
// ---------------------------------------------------------------------------

__device__ __align__(16) float    g_A[33554432];   // 256*128*32*32
__device__ __align__(16) float    g_B[33554432];
__device__ __align__(16) float    g_C[8388608];    // pooled buffers
__device__ __align__(16) uint32_t g_P[1048576];    // packed activations
__device__ __align__(16) uint32_t g_Wp[73728];     // packed weights (512*9*16)
__device__ double g_scale[512];
__device__ double g_shift[512];

// ---------------- conv0: fp32 3->128, 32x32, pad 1 -------------------------
// FMA chain ordered (ky, kx, ci) with ci innermost, padding taps skipped
// (== fma with exact zero). Intended to match XLA CPU Eigen im2col GEMM order.
__global__ __launch_bounds__(256) void conv0_kernel(
    const float* __restrict__ x, const float* __restrict__ w,
    float* __restrict__ out, int total) {
  int idx = blockIdx.x * blockDim.x + threadIdx.x;
  if (idx >= total) return;
  int x0 = idx & 31;
  int t  = idx >> 5;
  int y0 = t & 31; t >>= 5;
  int co = t & 127;
  int n  = t >> 7;
  float acc = 0.f;
#pragma unroll
  for (int ky = 0; ky < 3; ky++) {
    int yy = y0 + ky - 1;
    if ((unsigned)yy >= 32u) continue;
#pragma unroll
    for (int kx = 0; kx < 3; kx++) {
      int xx = x0 + kx - 1;
      if ((unsigned)xx >= 32u) continue;
#pragma unroll
      for (int ci = 0; ci < 3; ci++) {
        acc = fmaf(x[((n * 3 + ci) * 32 + yy) * 32 + xx],
                   w[((co * 3 + ci) * 3 + ky) * 3 + kx], acc);
      }
    }
  }
  out[idx] = acc;
}

// -------- per-channel batch stats (fp64) -> scale/shift (fp64) -------------
__global__ __launch_bounds__(256) void stats_kernel(
    const float* __restrict__ x, const float* __restrict__ g,
    const float* __restrict__ b, double* __restrict__ scale,
    double* __restrict__ shift, int N, int C, int HW) {
  int c = blockIdx.x;
  double s = 0.0, ss = 0.0;
  for (int n = 0; n < N; n++) {
    const float* p = x + ((size_t)n * C + c) * HW;
    for (int i = threadIdx.x; i < HW; i += blockDim.x) {
      double v = (double)p[i];
      s += v;
      ss += v * v;
    }
  }
  __shared__ double sh1[256], sh2[256];
  sh1[threadIdx.x] = s;
  sh2[threadIdx.x] = ss;
  __syncthreads();
  for (int o = 128; o > 0; o >>= 1) {
    if (threadIdx.x < o) {
      sh1[threadIdx.x] += sh1[threadIdx.x + o];
      sh2[threadIdx.x] += sh2[threadIdx.x + o];
    }
    __syncthreads();
  }
  if (threadIdx.x == 0) {
    double cnt  = (double)N * (double)HW;
    double mean = sh1[0] / cnt;
    double var  = sh2[0] / cnt - mean * mean;
    double sc   = (double)g[c] * rsqrt(var + 1e-5);
    scale[c] = sc;
    shift[c] = (double)b[c] - mean * sc;
  }
}

// ------ binarize(bn(x)) -> bitpack [n][y][x][C/32], fp64 threshold ---------
__global__ __launch_bounds__(256) void pack_kernel(
    const float* __restrict__ x, const double* __restrict__ scale,
    const double* __restrict__ shift, uint32_t* __restrict__ apk,
    int C, int H, int W, int total) {
  int idx = blockIdx.x * blockDim.x + threadIdx.x;
  if (idx >= total) return;
  int NW = C >> 5;
  int wrd = idx % NW;
  int p   = idx / NW;
  int x_  = p % W;
  int t   = p / W;
  int y   = t % H;
  int n   = t / H;
  uint32_t bits = 0;
#pragma unroll 8
  for (int k = 0; k < 32; k++) {
    int c = wrd * 32 + k;
    double z = (double)x[((n * C + c) * H + y) * W + x_] * scale[c] + shift[c];
    bits |= (z >= 0.0 ? 1u : 0u) << k;
  }
  apk[idx] = bits;
}

// ------------- binarize(weights) -> bitpack [co][tap][Ci/32] ---------------
__global__ __launch_bounds__(256) void packw_kernel(
    const float* __restrict__ w, uint32_t* __restrict__ wpk,
    int Ci, int total) {
  int idx = blockIdx.x * blockDim.x + threadIdx.x;
  if (idx >= total) return;
  int NW = Ci >> 5;
  int wrd = idx % NW;
  int t   = idx / NW;
  int tap = t % 9;
  int co  = t / 9;
  uint32_t bits = 0;
#pragma unroll 8
  for (int k = 0; k < 32; k++) {
    int ci = wrd * 32 + k;
    float v = w[(co * Ci + ci) * 9 + tap];
    bits |= (v >= 0.f ? 1u : 0u) << k;
  }
  wpk[idx] = bits;
}

// ---------------- binary conv 3x3 pad 1 via XNOR+popcount ------------------
__device__ __forceinline__ int popc4(uint4 a, uint4 b) {
  return __popc(a.x ^ b.x) + __popc(a.y ^ b.y) +
         __popc(a.z ^ b.z) + __popc(a.w ^ b.w);
}

template <int NW>
__global__ __launch_bounds__(256) void bconv_kernel(
    const uint32_t* __restrict__ apk, const uint32_t* __restrict__ wpk,
    float* __restrict__ out, int Co, int H, int W, int total) {
  int idx = blockIdx.x * blockDim.x + threadIdx.x;
  if (idx >= total) return;
  int x0 = idx % W;
  int t  = idx / W;
  int y0 = t % H; t /= H;
  int co = t % Co;
  int n  = t / Co;
  int cnt = 0, valid = 0;
  const uint4* wbase = reinterpret_cast<const uint4*>(wpk + co * 9 * NW);
#pragma unroll
  for (int dy = -1; dy <= 1; dy++) {
    int yy = y0 + dy;
    if ((unsigned)yy >= (unsigned)H) continue;
#pragma unroll
    for (int dx = -1; dx <= 1; dx++) {
      int xx = x0 + dx;
      if ((unsigned)xx >= (unsigned)W) continue;
      const uint4* a4 =
          reinterpret_cast<const uint4*>(apk + ((n * H + yy) * W + xx) * NW);
      const uint4* w4 = wbase + ((dy + 1) * 3 + (dx + 1)) * (NW / 4);
#pragma unroll
      for (int k = 0; k < NW / 4; k++) cnt += popc4(a4[k], w4[k]);
      valid++;
    }
  }
  out[idx] = (float)(valid * 32 * NW - 2 * cnt);   // exact even integer
}

// ---------------- 2x2 maxpool stride 2 -------------------------------------
__global__ __launch_bounds__(256) void pool_kernel(
    const float* __restrict__ in, float* __restrict__ out,
    int Ho, int Wo, int total) {
  int idx = blockIdx.x * blockDim.x + threadIdx.x;
  if (idx >= total) return;
  int x = idx % Wo;
  int t = idx / Wo;
  int y = t % Ho;
  int nc = t / Ho;
  int Hi = Ho * 2, Wi = Wo * 2;
  const float* p = in + ((size_t)nc * Hi + 2 * y) * Wi + 2 * x;
  float v0 = fmaxf(p[0], p[1]);
  float v1 = fmaxf(p[Wi], p[Wi + 1]);
  out[idx] = fmaxf(v0, v1);
}

// ------------- bn + hardtanh (final block output, fp64 path) ---------------
__global__ __launch_bounds__(256) void bn_ht_kernel(
    const float* __restrict__ in, const double* __restrict__ scale,
    const double* __restrict__ shift, float* __restrict__ out,
    int C, int HW, int total) {
  int idx = blockIdx.x * blockDim.x + threadIdx.x;
  if (idx >= total) return;
  int c = (idx / HW) % C;
  double z = (double)in[idx] * scale[c] + shift[c];
  z = fmin(1.0, fmax(-1.0, z));
  out[idx] = (float)z;
}

// ---------------- FC: [256,8192] @ [10,8192]^T + b (fp64 acc) --------------
__global__ __launch_bounds__(256) void fc_kernel(
    const float* __restrict__ h, const float* __restrict__ wfc,
    const float* __restrict__ bfc, float* __restrict__ out) {
  int gtid = blockIdx.x * blockDim.x + threadIdx.x;
  int warp = gtid >> 5;
  int lane = gtid & 31;
  if (warp >= 256 * 10) return;
  int n = warp / 10, k = warp % 10;
  const float* hp = h + (size_t)n * 8192;
  const float* wp = wfc + (size_t)k * 8192;
  double s = 0.0;
  for (int j = lane; j < 8192; j += 32) s += (double)hp[j] * (double)wp[j];
#pragma unroll
  for (int o = 16; o > 0; o >>= 1) s += __shfl_xor_sync(0xFFFFFFFFu, s, o);
  if (lane == 0) out[n * 10 + k] = (float)(s + (double)bfc[k]);
}

// ---------------------------------------------------------------------------
static inline int cdiv(int a, int b) { return (a + b - 1) / b; }

extern "C" void kernel_launch(void* const* d_in, const int* in_sizes, int n_in,
                              void* d_out, int out_size) {
  const float* x   = (const float*)d_in[0];
  const float* w0_ = (const float*)d_in[1];
  const float* g0  = (const float*)d_in[2];
  const float* b0  = (const float*)d_in[3];
  const float* wc1 = (const float*)d_in[4];
  const float* g1  = (const float*)d_in[5];
  const float* b1  = (const float*)d_in[6];
  const float* wc2 = (const float*)d_in[7];
  const float* g2  = (const float*)d_in[8];
  const float* b2  = (const float*)d_in[9];
  const float* wc3 = (const float*)d_in[10];
  const float* g3  = (const float*)d_in[11];
  const float* b3  = (const float*)d_in[12];
  const float* wc4 = (const float*)d_in[13];
  const float* g4  = (const float*)d_in[14];
  const float* b4  = (const float*)d_in[15];
  const float* wc5 = (const float*)d_in[16];
  const float* g5  = (const float*)d_in[17];
  const float* b5  = (const float*)d_in[18];
  const float* wfc = (const float*)d_in[19];
  const float* bfc = (const float*)d_in[20];
  float* out = (float*)d_out;

  float *A, *B, *C;
  double *sc, *sf;
  uint32_t *P, *Wp;
  cudaGetSymbolAddress((void**)&A, g_A);
  cudaGetSymbolAddress((void**)&B, g_B);
  cudaGetSymbolAddress((void**)&C, g_C);
  cudaGetSymbolAddress((void**)&P, g_P);
  cudaGetSymbolAddress((void**)&Wp, g_Wp);
  cudaGetSymbolAddress((void**)&sc, g_scale);
  cudaGetSymbolAddress((void**)&sf, g_shift);

  const int N = 256;
  const int TB = 256;

  // ---- conv0 + bn0 stats ----
  {
    int total = N * 128 * 32 * 32;
    conv0_kernel<<<cdiv(total, TB), TB>>>(x, w0_, A, total);
    stats_kernel<<<128, TB>>>(A, g0, b0, sc, sf, N, 128, 32 * 32);
  }
  // ---- block1: bconv 128->128 @32, pool->16, bn1 ----
  {
    int tp = N * 32 * 32 * 4;
    pack_kernel<<<cdiv(tp, TB), TB>>>(A, sc, sf, P, 128, 32, 32, tp);
    int tw = 128 * 9 * 4;
    packw_kernel<<<cdiv(tw, TB), TB>>>(wc1, Wp, 128, tw);
    int tc = N * 128 * 32 * 32;
    bconv_kernel<4><<<cdiv(tc, TB), TB>>>(P, Wp, B, 128, 32, 32, tc);
    int to = N * 128 * 16 * 16;
    pool_kernel<<<cdiv(to, TB), TB>>>(B, C, 16, 16, to);
    stats_kernel<<<128, TB>>>(C, g1, b1, sc, sf, N, 128, 16 * 16);
  }
  // ---- block2: bconv 128->256 @16, bn2 ----
  {
    int tp = N * 16 * 16 * 4;
    pack_kernel<<<cdiv(tp, TB), TB>>>(C, sc, sf, P, 128, 16, 16, tp);
    int tw = 256 * 9 * 4;
    packw_kernel<<<cdiv(tw, TB), TB>>>(wc2, Wp, 128, tw);
    int tc = N * 256 * 16 * 16;
    bconv_kernel<4><<<cdiv(tc, TB), TB>>>(P, Wp, A, 256, 16, 16, tc);
    stats_kernel<<<256, TB>>>(A, g2, b2, sc, sf, N, 256, 16 * 16);
  }
  // ---- block3: bconv 256->256 @16, pool->8, bn3 ----
  {
    int tp = N * 16 * 16 * 8;
    pack_kernel<<<cdiv(tp, TB), TB>>>(A, sc, sf, P, 256, 16, 16, tp);
    int tw = 256 * 9 * 8;
    packw_kernel<<<cdiv(tw, TB), TB>>>(wc3, Wp, 256, tw);
    int tc = N * 256 * 16 * 16;
    bconv_kernel<8><<<cdiv(tc, TB), TB>>>(P, Wp, B, 256, 16, 16, tc);
    int to = N * 256 * 8 * 8;
    pool_kernel<<<cdiv(to, TB), TB>>>(B, C, 8, 8, to);
    stats_kernel<<<256, TB>>>(C, g3, b3, sc, sf, N, 256, 8 * 8);
  }
  // ---- block4: bconv 256->512 @8, bn4 ----
  {
    int tp = N * 8 * 8 * 8;
    pack_kernel<<<cdiv(tp, TB), TB>>>(C, sc, sf, P, 256, 8, 8, tp);
    int tw = 512 * 9 * 8;
    packw_kernel<<<cdiv(tw, TB), TB>>>(wc4, Wp, 256, tw);
    int tc = N * 512 * 8 * 8;
    bconv_kernel<8><<<cdiv(tc, TB), TB>>>(P, Wp, A, 512, 8, 8, tc);
    stats_kernel<<<512, TB>>>(A, g4, b4, sc, sf, N, 512, 8 * 8);
  }
  // ---- block5: bconv 512->512 @8, pool->4, bn5 + hardtanh ----
  {
    int tp = N * 8 * 8 * 16;
    pack_kernel<<<cdiv(tp, TB), TB>>>(A, sc, sf, P, 512, 8, 8, tp);
    int tw = 512 * 9 * 16;
    packw_kernel<<<cdiv(tw, TB), TB>>>(wc5, Wp, 512, tw);
    int tc = N * 512 * 8 * 8;
    bconv_kernel<16><<<cdiv(tc, TB), TB>>>(P, Wp, B, 512, 8, 8, tc);
    int to = N * 512 * 4 * 4;
    pool_kernel<<<cdiv(to, TB), TB>>>(B, C, 4, 4, to);
    stats_kernel<<<512, TB>>>(C, g5, b5, sc, sf, N, 512, 4 * 4);
    bn_ht_kernel<<<cdiv(to, TB), TB>>>(C, sc, sf, A, 512, 16, to);
  }
  // ---- FC ----
  {
    int threads = 256 * 10 * 32;
    fc_kernel<<<cdiv(threads, TB), TB>>>(A, wfc, bfc, out);
  }
}

// round 3
// speedup vs baseline: 1.2285x; 1.2285x over previous
#include <cuda_runtime.h>
#include <cstdint>

// ---------------------------------------------------------------------------
// VGG-small 1w1a forward, batch 256. Optimized round:
//  - conv0: smem-tiled, sliding register window, bit-identical fma order
//  - bconv: smem weights->regs, smem activation rows, sliding uint4 window,
//           channel-split via shfl, fused 2x2 maxpool
//  - pack:  coalesced loads (warp = 32 consecutive pixels, c-loop inner)
// ---------------------------------------------------------------------------

__device__ __align__(16) float    g_A[33554432];   // 256*128*32*32 floats
__device__ __align__(16) float    g_C[8388608];    // pooled / secondary
__device__ __align__(16) uint32_t g_P[1048576];    // packed activations
__device__ __align__(16) uint32_t g_Wp[73728];     // packed weights
__device__ double g_scale[512];
__device__ double g_shift[512];

// ---------------- conv0: fp32 3->128, 32x32, pad 1 -------------------------
__global__ __launch_bounds__(256) void conv0_kernel(
    const float* __restrict__ x, const float* __restrict__ w,
    float* __restrict__ out) {
  __shared__ float sW[128 * 27];
  __shared__ float sX[3][3][34];   // [ci][row][halo col]
  int bx = blockIdx.x;
  int y = bx & 31, n = bx >> 5;
  int tid = threadIdx.x;
  for (int i = tid; i < 3456; i += 256) sW[i] = w[i];
  for (int i = tid; i < 3 * 3 * 34; i += 256) {
    int col = i % 34;
    int r = (i / 34) % 3;
    int ci = i / (34 * 3);
    int gy = y - 1 + r;
    int gx = col - 1;
    float v = 0.f;
    if (gy >= 0 && gy < 32 && gx >= 0 && gx < 32)
      v = x[((n * 3 + ci) * 32 + gy) * 32 + gx];
    sX[ci][r][col] = v;
  }
  __syncthreads();
  int co = tid >> 1, xh = tid & 1, x0 = xh * 16;
  float wr[27];
#pragma unroll
  for (int ky = 0; ky < 3; ky++)
#pragma unroll
    for (int kx = 0; kx < 3; kx++)
#pragma unroll
      for (int ci = 0; ci < 3; ci++)
        wr[(ky * 3 + kx) * 3 + ci] = sW[((co * 3 + ci) * 3 + ky) * 3 + kx];
  float a[3][3][3];  // [row][window col][ci]
#pragma unroll
  for (int r = 0; r < 3; r++)
#pragma unroll
    for (int ci = 0; ci < 3; ci++) {
      a[r][0][ci] = sX[ci][r][x0];
      a[r][1][ci] = sX[ci][r][x0 + 1];
    }
  float* obase = out + (((size_t)n * 128 + co) * 32 + y) * 32;
#pragma unroll
  for (int xi = 0; xi < 16; xi++) {
    int xc = x0 + xi;
#pragma unroll
    for (int r = 0; r < 3; r++)
#pragma unroll
      for (int ci = 0; ci < 3; ci++) a[r][2][ci] = sX[ci][r][xc + 2];
    float acc = 0.f;
#pragma unroll
    for (int ky = 0; ky < 3; ky++)
#pragma unroll
      for (int kx = 0; kx < 3; kx++)
#pragma unroll
        for (int ci = 0; ci < 3; ci++)
          acc = fmaf(a[ky][kx][ci], wr[(ky * 3 + kx) * 3 + ci], acc);
    obase[xc] = acc;
#pragma unroll
    for (int r = 0; r < 3; r++)
#pragma unroll
      for (int ci = 0; ci < 3; ci++) {
        a[r][0][ci] = a[r][1][ci];
        a[r][1][ci] = a[r][2][ci];
      }
  }
}

// -------- per-channel batch stats (fp64) -> scale/shift (fp64) -------------
__global__ __launch_bounds__(256) void stats_kernel(
    const float* __restrict__ x, const float* __restrict__ g,
    const float* __restrict__ b, double* __restrict__ scale,
    double* __restrict__ shift, int N, int C, int HW) {
  int c = blockIdx.x;
  double s = 0.0, ss = 0.0;
  for (int n = 0; n < N; n++) {
    const float* p = x + ((size_t)n * C + c) * HW;
    for (int i = threadIdx.x; i < HW; i += blockDim.x) {
      double v = (double)p[i];
      s += v;
      ss += v * v;
    }
  }
  __shared__ double sh1[256], sh2[256];
  sh1[threadIdx.x] = s;
  sh2[threadIdx.x] = ss;
  __syncthreads();
  for (int o = 128; o > 0; o >>= 1) {
    if (threadIdx.x < o) {
      sh1[threadIdx.x] += sh1[threadIdx.x + o];
      sh2[threadIdx.x] += sh2[threadIdx.x + o];
    }
    __syncthreads();
  }
  if (threadIdx.x == 0) {
    double cnt = (double)N * (double)HW;
    double mean = sh1[0] / cnt;
    double var = sh2[0] / cnt - mean * mean;
    double sc = (double)g[c] * rsqrt(var + 1e-5);
    scale[c] = sc;
    shift[c] = (double)b[c] - mean * sc;
  }
}

// ------ binarize(bn(x)) -> bitpack [pixel][C/32], coalesced ----------------
__global__ __launch_bounds__(256) void pack2_kernel(
    const float* __restrict__ x, const double* __restrict__ scale,
    const double* __restrict__ shift, uint32_t* __restrict__ apk,
    int C, int HW, int NW) {
  int gt = blockIdx.x * 256 + threadIdx.x;
  int lane = gt & 31;
  int gw = gt >> 5;
  int wrd = gw % NW;
  int chunk = gw / NW;
  int pixel = chunk * 32 + lane;
  int n = pixel / HW, hw = pixel % HW;
  const float* base = x + ((size_t)n * C + wrd * 32) * HW + hw;
  const double* scp = scale + wrd * 32;
  const double* sfp = shift + wrd * 32;
  uint32_t bits = 0;
#pragma unroll 8
  for (int k = 0; k < 32; k++) {
    double z = (double)base[(size_t)k * HW] * scp[k] + sfp[k];
    bits |= (z >= 0.0 ? 1u : 0u) << k;
  }
  apk[(size_t)pixel * NW + wrd] = bits;
}

// ------------- binarize(weights) -> bitpack [co][tap][Ci/32] ---------------
__global__ __launch_bounds__(256) void packw_kernel(
    const float* __restrict__ w, uint32_t* __restrict__ wpk,
    int Ci, int total) {
  int idx = blockIdx.x * blockDim.x + threadIdx.x;
  if (idx >= total) return;
  int NW = Ci >> 5;
  int wrd = idx % NW;
  int t = idx / NW;
  int tap = t % 9;
  int co = t / 9;
  uint32_t bits = 0;
#pragma unroll 8
  for (int k = 0; k < 32; k++) {
    float v = w[(co * Ci + (wrd * 32 + k)) * 9 + tap];
    bits |= (v >= 0.f ? 1u : 0u) << k;
  }
  wpk[idx] = bits;
}

// ---------------- binary conv 3x3 pad 1 (+ fused maxpool) ------------------
__device__ __forceinline__ int popc4(uint4 a, uint4 b) {
  return __popc(a.x ^ b.x) + __popc(a.y ^ b.y) +
         __popc(a.z ^ b.z) + __popc(a.w ^ b.w);
}

template <int CO, int CO_G, int H, int W, int NW, int SPLIT, int YT, int XT,
          bool POOL>
__global__ __launch_bounds__(CO_G* SPLIT*(W / XT)) void bconv2_kernel(
    const uint32_t* __restrict__ apk, const uint32_t* __restrict__ wpk,
    float* __restrict__ out) {
  constexpr int NTH = CO_G * SPLIT * (W / XT);
  constexpr int CGRP = CO / CO_G;
  __shared__ uint32_t sW[CO_G * 9 * NW];
  __shared__ uint32_t sA[(YT + 2) * W * NW];
  int bx = blockIdx.x;
  int cg = bx % CGRP;
  int yg = (bx / CGRP) % (H / YT);
  int n = bx / (CGRP * (H / YT));
  int tid = threadIdx.x;
  // weights -> smem
  const uint4* wsrc = reinterpret_cast<const uint4*>(
      wpk + (size_t)cg * CO_G * 9 * NW);
  for (int i = tid; i < CO_G * 9 * NW / 4; i += NTH)
    reinterpret_cast<uint4*>(sW)[i] = wsrc[i];
  // activation rows ybase-1 .. ybase+YT -> smem (zero for OOB rows)
  int ybase = yg * YT;
  constexpr int RW4 = W * NW / 4;  // uint4 per row
  for (int i = tid; i < (YT + 2) * RW4; i += NTH) {
    int r = i / RW4;
    int gy = ybase - 1 + r;
    uint4 v = make_uint4(0u, 0u, 0u, 0u);
    if (gy >= 0 && gy < H)
      v = reinterpret_cast<const uint4*>(
          apk + ((size_t)(n * H + gy) * W) * NW)[i % RW4];
    reinterpret_cast<uint4*>(sA)[i] = v;
  }
  __syncthreads();
  int slice = tid % SPLIT;
  int t2 = tid / SPLIT;
  int xg = t2 % (W / XT);
  int co_l = t2 / (W / XT);
  int x0 = xg * XT;
  uint4 wt[9];
#pragma unroll
  for (int t = 0; t < 9; t++)
    wt[t] = *reinterpret_cast<const uint4*>(
        &sW[(co_l * 9 + t) * NW + slice * 4]);
  int co = cg * CO_G + co_l;
  float pmax[XT / 2];
  float tmpv = 0.f;
#pragma unroll
  for (int ry = 0; ry < YT; ry++) {
    int y = ybase + ry;
    int rv0 = (y > 0) ? 1 : 0;
    int rv2 = (y < H - 1) ? 1 : 0;
    int nrows = 1 + rv0 + rv2;
    uint4 aL[3], aM[3], aR[3];
#pragma unroll
    for (int rr = 0; rr < 3; rr++) {
      aM[rr] = *reinterpret_cast<const uint4*>(
          &sA[((ry + rr) * W + x0) * NW + slice * 4]);
      aL[rr] = (x0 > 0)
                   ? *reinterpret_cast<const uint4*>(
                         &sA[((ry + rr) * W + x0 - 1) * NW + slice * 4])
                   : make_uint4(0u, 0u, 0u, 0u);
    }
#pragma unroll
    for (int xi = 0; xi < XT; xi++) {
      int xc = x0 + xi;
      int cl = (xc > 0) ? 1 : 0;
      int cr = (xc < W - 1) ? 1 : 0;
#pragma unroll
      for (int rr = 0; rr < 3; rr++)
        aR[rr] = cr ? *reinterpret_cast<const uint4*>(
                          &sA[((ry + rr) * W + xc + 1) * NW + slice * 4])
                    : make_uint4(0u, 0u, 0u, 0u);
      int cnt = 0;
#pragma unroll
      for (int rr = 0; rr < 3; rr++) {
        int rvalid = (rr == 0) ? rv0 : ((rr == 2) ? rv2 : 1);
        if (rvalid) {
          if (cl) cnt += popc4(aL[rr], wt[rr * 3 + 0]);
          cnt += popc4(aM[rr], wt[rr * 3 + 1]);
          if (cr) cnt += popc4(aR[rr], wt[rr * 3 + 2]);
        }
      }
#pragma unroll
      for (int o = 1; o < SPLIT; o <<= 1)
        cnt += __shfl_xor_sync(0xffffffffu, cnt, o);
      int ncols = 1 + cl + cr;
      float val = (float)(nrows * ncols * 32 * NW - 2 * cnt);
      if (POOL) {
        if ((xi & 1) == 0) {
          tmpv = val;
        } else {
          float m2 = fmaxf(tmpv, val);
          if ((ry & 1) == 0) {
            pmax[xi >> 1] = m2;
          } else {
            float m = fmaxf(pmax[xi >> 1], m2);
            if (slice == 0)
              out[(((size_t)n * CO + co) * (H / 2) + (y >> 1)) * (W / 2) +
                  (xc >> 1)] = m;
          }
        }
      } else {
        if (slice == 0)
          out[(((size_t)n * CO + co) * H + y) * W + xc] = val;
      }
#pragma unroll
      for (int rr = 0; rr < 3; rr++) {
        aL[rr] = aM[rr];
        aM[rr] = aR[rr];
      }
    }
  }
}

// ------------- bn + hardtanh (final block output, fp64 path) ---------------
__global__ __launch_bounds__(256) void bn_ht_kernel(
    const float* __restrict__ in, const double* __restrict__ scale,
    const double* __restrict__ shift, float* __restrict__ out,
    int C, int HW, int total) {
  int idx = blockIdx.x * blockDim.x + threadIdx.x;
  if (idx >= total) return;
  int c = (idx / HW) % C;
  double z = (double)in[idx] * scale[c] + shift[c];
  z = fmin(1.0, fmax(-1.0, z));
  out[idx] = (float)z;
}

// ---------------- FC: [256,8192] @ [10,8192]^T + b (fp64 acc) --------------
__global__ __launch_bounds__(256) void fc_kernel(
    const float* __restrict__ h, const float* __restrict__ wfc,
    const float* __restrict__ bfc, float* __restrict__ out) {
  int gtid = blockIdx.x * blockDim.x + threadIdx.x;
  int warp = gtid >> 5;
  int lane = gtid & 31;
  if (warp >= 256 * 10) return;
  int n = warp / 10, k = warp % 10;
  const float* hp = h + (size_t)n * 8192;
  const float* wp = wfc + (size_t)k * 8192;
  double s = 0.0;
  for (int j = lane; j < 8192; j += 32) s += (double)hp[j] * (double)wp[j];
#pragma unroll
  for (int o = 16; o > 0; o >>= 1) s += __shfl_xor_sync(0xFFFFFFFFu, s, o);
  if (lane == 0) out[n * 10 + k] = (float)(s + (double)bfc[k]);
}

// ---------------------------------------------------------------------------
static inline int cdiv(int a, int b) { return (a + b - 1) / b; }

extern "C" void kernel_launch(void* const* d_in, const int* in_sizes, int n_in,
                              void* d_out, int out_size) {
  const float* x   = (const float*)d_in[0];
  const float* w0_ = (const float*)d_in[1];
  const float* g0  = (const float*)d_in[2];
  const float* b0  = (const float*)d_in[3];
  const float* wc1 = (const float*)d_in[4];
  const float* g1  = (const float*)d_in[5];
  const float* b1  = (const float*)d_in[6];
  const float* wc2 = (const float*)d_in[7];
  const float* g2  = (const float*)d_in[8];
  const float* b2  = (const float*)d_in[9];
  const float* wc3 = (const float*)d_in[10];
  const float* g3  = (const float*)d_in[11];
  const float* b3  = (const float*)d_in[12];
  const float* wc4 = (const float*)d_in[13];
  const float* g4  = (const float*)d_in[14];
  const float* b4  = (const float*)d_in[15];
  const float* wc5 = (const float*)d_in[16];
  const float* g5  = (const float*)d_in[17];
  const float* b5  = (const float*)d_in[18];
  const float* wfc = (const float*)d_in[19];
  const float* bfc = (const float*)d_in[20];
  float* out = (float*)d_out;

  float *A, *C;
  double *sc, *sf;
  uint32_t *P, *Wp;
  cudaGetSymbolAddress((void**)&A, g_A);
  cudaGetSymbolAddress((void**)&C, g_C);
  cudaGetSymbolAddress((void**)&P, g_P);
  cudaGetSymbolAddress((void**)&Wp, g_Wp);
  cudaGetSymbolAddress((void**)&sc, g_scale);
  cudaGetSymbolAddress((void**)&sf, g_shift);

  const int N = 256;
  const int TB = 256;

  // ---- conv0 + bn0 stats ----
  conv0_kernel<<<N * 32, TB>>>(x, w0_, A);
  stats_kernel<<<128, TB>>>(A, g0, b0, sc, sf, N, 128, 1024);

  // ---- block1: pack(A,128@32x32) -> bconv 128->128 +pool -> C ----
  pack2_kernel<<<N * 1024 * 4 / TB, TB>>>(A, sc, sf, P, 128, 1024, 4);
  packw_kernel<<<cdiv(128 * 9 * 4, TB), TB>>>(wc1, Wp, 128, 128 * 9 * 4);
  bconv2_kernel<128, 128, 32, 32, 4, 1, 4, 16, true>
      <<<N * 8 * 1, TB>>>(P, Wp, C);
  stats_kernel<<<128, TB>>>(C, g1, b1, sc, sf, N, 128, 256);

  // ---- block2: pack(C,128@16x16) -> bconv 128->256 -> A ----
  pack2_kernel<<<N * 256 * 4 / TB, TB>>>(C, sc, sf, P, 128, 256, 4);
  packw_kernel<<<cdiv(256 * 9 * 4, TB), TB>>>(wc2, Wp, 128, 256 * 9 * 4);
  bconv2_kernel<256, 256, 16, 16, 4, 1, 4, 16, false>
      <<<N * 4 * 1, TB>>>(P, Wp, A);
  stats_kernel<<<256, TB>>>(A, g2, b2, sc, sf, N, 256, 256);

  // ---- block3: pack(A,256@16x16) -> bconv 256->256 +pool -> C ----
  pack2_kernel<<<N * 256 * 8 / TB, TB>>>(A, sc, sf, P, 256, 256, 8);
  packw_kernel<<<cdiv(256 * 9 * 8, TB), TB>>>(wc3, Wp, 256, 256 * 9 * 8);
  bconv2_kernel<256, 128, 16, 16, 8, 2, 4, 16, true>
      <<<N * 4 * 2, TB>>>(P, Wp, C);
  stats_kernel<<<256, TB>>>(C, g3, b3, sc, sf, N, 256, 64);

  // ---- block4: pack(C,256@8x8) -> bconv 256->512 -> A ----
  pack2_kernel<<<N * 64 * 8 / TB, TB>>>(C, sc, sf, P, 256, 64, 8);
  packw_kernel<<<cdiv(512 * 9 * 8, TB), TB>>>(wc4, Wp, 256, 512 * 9 * 8);
  bconv2_kernel<512, 128, 8, 8, 8, 2, 4, 8, false>
      <<<N * 2 * 4, TB>>>(P, Wp, A);
  stats_kernel<<<512, TB>>>(A, g4, b4, sc, sf, N, 512, 64);

  // ---- block5: pack(A,512@8x8) -> bconv 512->512 +pool -> C ----
  pack2_kernel<<<N * 64 * 16 / TB, TB>>>(A, sc, sf, P, 512, 64, 16);
  packw_kernel<<<cdiv(512 * 9 * 16, TB), TB>>>(wc5, Wp, 512, 512 * 9 * 16);
  bconv2_kernel<512, 64, 8, 8, 16, 4, 4, 8, true>
      <<<N * 2 * 8, TB>>>(P, Wp, C);
  stats_kernel<<<512, TB>>>(C, g5, b5, sc, sf, N, 512, 16);

  // ---- bn5 + hardtanh -> A, then FC ----
  {
    int to = N * 512 * 16;
    bn_ht_kernel<<<cdiv(to, TB), TB>>>(C, sc, sf, A, 512, 16, to);
    fc_kernel<<<cdiv(N * 10 * 32, TB), TB>>>(A, wfc, bfc, out);
  }
}

// round 4
// speedup vs baseline: 1.5030x; 1.2235x over previous
#include <cuda_runtime.h>
#include <cstdint>

// ---------------------------------------------------------------------------
// VGG-small 1w1a forward, batch 256.
//  conv0 fp32 tiled -> fp64 stats/pack (layer0 only) ->
//  [bconv(int16 out, fused pool) -> int stats -> int pack] x5 -> bn+ht -> fc
//  Binary-layer BN thresholds converted to exact integer predicates.
// ---------------------------------------------------------------------------

__device__ __align__(16) float    g_A[33554432];   // also reused as int16
__device__ __align__(16) float    g_C[8388608];    // also reused as int16
__device__ __align__(16) uint32_t g_P[1048576];    // packed activations
__device__ __align__(16) uint32_t g_Wp[147456];    // packed weights (all 5)
__device__ double g_scale[512];
__device__ double g_shift[512];
__device__ int    g_ithr[512];
__device__ int    g_isgn[512];
__device__ double g_part[4096];                    // stats0 partials

// ---------------- conv0: fp32 3->128, 32x32, pad 1 -------------------------
__global__ __launch_bounds__(256) void conv0_kernel(
    const float* __restrict__ x, const float* __restrict__ w,
    float* __restrict__ out) {
  __shared__ float sW[128 * 27];
  __shared__ float sX[3][3][34];
  int bx = blockIdx.x;
  int y = bx & 31, n = bx >> 5;
  int tid = threadIdx.x;
  for (int i = tid; i < 3456; i += 256) sW[i] = w[i];
  for (int i = tid; i < 3 * 3 * 34; i += 256) {
    int col = i % 34;
    int r = (i / 34) % 3;
    int ci = i / (34 * 3);
    int gy = y - 1 + r, gx = col - 1;
    float v = 0.f;
    if (gy >= 0 && gy < 32 && gx >= 0 && gx < 32)
      v = x[((n * 3 + ci) * 32 + gy) * 32 + gx];
    sX[ci][r][col] = v;
  }
  __syncthreads();
  int co = tid >> 1, xh = tid & 1, x0 = xh * 16;
  float wr[27];
#pragma unroll
  for (int ky = 0; ky < 3; ky++)
#pragma unroll
    for (int kx = 0; kx < 3; kx++)
#pragma unroll
      for (int ci = 0; ci < 3; ci++)
        wr[(ky * 3 + kx) * 3 + ci] = sW[((co * 3 + ci) * 3 + ky) * 3 + kx];
  float a[3][3][3];
#pragma unroll
  for (int r = 0; r < 3; r++)
#pragma unroll
    for (int ci = 0; ci < 3; ci++) {
      a[r][0][ci] = sX[ci][r][x0];
      a[r][1][ci] = sX[ci][r][x0 + 1];
    }
  float* obase = out + (((size_t)n * 128 + co) * 32 + y) * 32;
#pragma unroll
  for (int xi = 0; xi < 16; xi++) {
    int xc = x0 + xi;
#pragma unroll
    for (int r = 0; r < 3; r++)
#pragma unroll
      for (int ci = 0; ci < 3; ci++) a[r][2][ci] = sX[ci][r][xc + 2];
    float acc = 0.f;
#pragma unroll
    for (int ky = 0; ky < 3; ky++)
#pragma unroll
      for (int kx = 0; kx < 3; kx++)
#pragma unroll
        for (int ci = 0; ci < 3; ci++)
          acc = fmaf(a[ky][kx][ci], wr[(ky * 3 + kx) * 3 + ci], acc);
    obase[xc] = acc;
#pragma unroll
    for (int r = 0; r < 3; r++)
#pragma unroll
      for (int ci = 0; ci < 3; ci++) {
        a[r][0][ci] = a[r][1][ci];
        a[r][1][ci] = a[r][2][ci];
      }
  }
}

// ----------- layer0 stats: fp64, chunked, deterministic 2-stage ------------
__global__ __launch_bounds__(256) void stats0_partial(
    const float* __restrict__ x, double* __restrict__ part,
    int C, int HW, int CH) {
  int c = blockIdx.x, ch = blockIdx.y;
  double s = 0.0, ss = 0.0;
  for (int n = ch * CH; n < (ch + 1) * CH; n++) {
    const float* p = x + ((size_t)n * C + c) * HW;
    for (int i = threadIdx.x; i < HW; i += 256) {
      double v = (double)p[i];
      s += v;
      ss += v * v;
    }
  }
  __shared__ double sh1[256], sh2[256];
  sh1[threadIdx.x] = s;
  sh2[threadIdx.x] = ss;
  __syncthreads();
  for (int o = 128; o > 0; o >>= 1) {
    if (threadIdx.x < o) {
      sh1[threadIdx.x] += sh1[threadIdx.x + o];
      sh2[threadIdx.x] += sh2[threadIdx.x + o];
    }
    __syncthreads();
  }
  if (threadIdx.x == 0) {
    part[c * gridDim.y + ch] = sh1[0];
    part[C * gridDim.y + c * gridDim.y + ch] = sh2[0];
  }
}

__global__ void stats0_fin(const double* __restrict__ part,
                           const float* __restrict__ g,
                           const float* __restrict__ b,
                           double* __restrict__ scale,
                           double* __restrict__ shift, int C, int CHUNKS,
                           double cnt) {
  int c = blockIdx.x * blockDim.x + threadIdx.x;
  if (c >= C) return;
  double S = 0.0, SS = 0.0;
  for (int ch = 0; ch < CHUNKS; ch++) {
    S += part[c * CHUNKS + ch];
    SS += part[C * CHUNKS + c * CHUNKS + ch];
  }
  double mean = S / cnt;
  double var = SS / cnt - mean * mean;
  double sc = (double)g[c] * rsqrt(var + 1e-5);
  scale[c] = sc;
  shift[c] = (double)b[c] - mean * sc;
}

// -------- layer0 pack: fp64 threshold on continuous conv0 output -----------
__global__ __launch_bounds__(256) void pack0_kernel(
    const float* __restrict__ x, const double* __restrict__ scale,
    const double* __restrict__ shift, uint32_t* __restrict__ apk,
    int C, int HW, int NW) {
  int gt = blockIdx.x * 256 + threadIdx.x;
  int lane = gt & 31;
  int gw = gt >> 5;
  int wrd = gw % NW;
  int chunk = gw / NW;
  int pixel = chunk * 32 + lane;
  int n = pixel / HW, hw = pixel % HW;
  const float* base = x + ((size_t)n * C + wrd * 32) * HW + hw;
  const double* scp = scale + wrd * 32;
  const double* sfp = shift + wrd * 32;
  uint32_t bits = 0;
#pragma unroll 8
  for (int k = 0; k < 32; k++) {
    double z = (double)base[(size_t)k * HW] * scp[k] + sfp[k];
    bits |= (z >= 0.0 ? 1u : 0u) << k;
  }
  apk[(size_t)pixel * NW + wrd] = bits;
}

// -------- binary-layer stats: exact int64 accumulation ---------------------
__global__ __launch_bounds__(256) void stats_int_kernel(
    const short* __restrict__ x, const float* __restrict__ g,
    const float* __restrict__ b, double* __restrict__ scale,
    double* __restrict__ shift, int* __restrict__ thr, int* __restrict__ sgn,
    int N, int C, int HW) {
  int c = blockIdx.x;
  long long s = 0, ss = 0;
  for (int n = 0; n < N; n++) {
    const short* p = x + ((size_t)n * C + c) * HW;
    for (int i = threadIdx.x; i < HW; i += 256) {
      int v = p[i];
      s += v;
      ss += (long long)(v * v);
    }
  }
  __shared__ long long sh1[256], sh2[256];
  sh1[threadIdx.x] = s;
  sh2[threadIdx.x] = ss;
  __syncthreads();
  for (int o = 128; o > 0; o >>= 1) {
    if (threadIdx.x < o) {
      sh1[threadIdx.x] += sh1[threadIdx.x + o];
      sh2[threadIdx.x] += sh2[threadIdx.x + o];
    }
    __syncthreads();
  }
  if (threadIdx.x == 0) {
    double cnt = (double)N * (double)HW;
    double mean = (double)sh1[0] / cnt;
    double var = (double)sh2[0] / cnt - mean * mean;
    double sc = (double)g[c] * rsqrt(var + 1e-5);
    double sf = (double)b[c] - mean * sc;
    scale[c] = sc;
    shift[c] = sf;
    double T = -sf / sc;   // z>=0  <=>  v >= T (sc>0)  /  v <= T (sc<0)
    if (sc > 0.0) {
      thr[c] = (int)ceil(T);
      sgn[c] = 1;
    } else {
      thr[c] = (int)floor(T);
      sgn[c] = 0;
    }
  }
}

// -------- binary-layer pack: pure integer predicate ------------------------
__global__ __launch_bounds__(256) void pack_int_kernel(
    const short* __restrict__ x, const int* __restrict__ thr,
    const int* __restrict__ sgn, uint32_t* __restrict__ apk,
    int C, int HW, int NW) {
  int gt = blockIdx.x * 256 + threadIdx.x;
  int lane = gt & 31;
  int gw = gt >> 5;
  int wrd = gw % NW;
  int chunk = gw / NW;
  int pixel = chunk * 32 + lane;
  int n = pixel / HW, hw = pixel % HW;
  const short* base = x + ((size_t)n * C + wrd * 32) * HW + hw;
  const int* tp = thr + wrd * 32;
  const int* sp = sgn + wrd * 32;
  uint32_t bits = 0;
#pragma unroll 8
  for (int k = 0; k < 32; k++) {
    int v = base[(size_t)k * HW];
    bool bit = sp[k] ? (v >= tp[k]) : (v <= tp[k]);
    bits |= (bit ? 1u : 0u) << k;
  }
  apk[(size_t)pixel * NW + wrd] = bits;
}

// ------------- binarize(weights) -> bitpack [co][tap][Ci/32] ---------------
__global__ __launch_bounds__(256) void packw_kernel(
    const float* __restrict__ w, uint32_t* __restrict__ wpk,
    int Ci, int total) {
  int idx = blockIdx.x * blockDim.x + threadIdx.x;
  if (idx >= total) return;
  int NW = Ci >> 5;
  int wrd = idx % NW;
  int t = idx / NW;
  int tap = t % 9;
  int co = t / 9;
  uint32_t bits = 0;
#pragma unroll 8
  for (int k = 0; k < 32; k++) {
    float v = w[(co * Ci + (wrd * 32 + k)) * 9 + tap];
    bits |= (v >= 0.f ? 1u : 0u) << k;
  }
  wpk[idx] = bits;
}

// ---------------- binary conv 3x3 pad 1 (+ fused maxpool), int16 out -------
__device__ __forceinline__ int popc4(uint4 a, uint4 b) {
  return __popc(a.x ^ b.x) + __popc(a.y ^ b.y) +
         __popc(a.z ^ b.z) + __popc(a.w ^ b.w);
}

template <int CO, int CO_G, int H, int W, int NW, int SPLIT, int YT, int XT,
          bool POOL>
__global__ __launch_bounds__(CO_G* SPLIT*(W / XT)) void bconv2_kernel(
    const uint32_t* __restrict__ apk, const uint32_t* __restrict__ wpk,
    short* __restrict__ out) {
  constexpr int NTH = CO_G * SPLIT * (W / XT);
  constexpr int CGRP = CO / CO_G;
  __shared__ uint32_t sW[CO_G * 9 * NW];
  __shared__ uint32_t sA[(YT + 2) * W * NW];
  int bx = blockIdx.x;
  int cg = bx % CGRP;
  int yg = (bx / CGRP) % (H / YT);
  int n = bx / (CGRP * (H / YT));
  int tid = threadIdx.x;
  const uint4* wsrc =
      reinterpret_cast<const uint4*>(wpk + (size_t)cg * CO_G * 9 * NW);
  for (int i = tid; i < CO_G * 9 * NW / 4; i += NTH)
    reinterpret_cast<uint4*>(sW)[i] = wsrc[i];
  int ybase = yg * YT;
  constexpr int RW4 = W * NW / 4;
  for (int i = tid; i < (YT + 2) * RW4; i += NTH) {
    int r = i / RW4;
    int gy = ybase - 1 + r;
    uint4 v = make_uint4(0u, 0u, 0u, 0u);
    if (gy >= 0 && gy < H)
      v = reinterpret_cast<const uint4*>(
          apk + ((size_t)(n * H + gy) * W) * NW)[i % RW4];
    reinterpret_cast<uint4*>(sA)[i] = v;
  }
  __syncthreads();
  int slice = tid % SPLIT;
  int t2 = tid / SPLIT;
  int xg = t2 % (W / XT);
  int co_l = t2 / (W / XT);
  int x0 = xg * XT;
  uint4 wt[9];
#pragma unroll
  for (int t = 0; t < 9; t++)
    wt[t] = *reinterpret_cast<const uint4*>(
        &sW[(co_l * 9 + t) * NW + slice * 4]);
  int co = cg * CO_G + co_l;
  int pmax[XT / 2];
  int tmpv = 0;
#pragma unroll
  for (int ry = 0; ry < YT; ry++) {
    int y = ybase + ry;
    int rv0 = (y > 0) ? 1 : 0;
    int rv2 = (y < H - 1) ? 1 : 0;
    int nrows = 1 + rv0 + rv2;
    uint4 aL[3], aM[3], aR[3];
#pragma unroll
    for (int rr = 0; rr < 3; rr++) {
      aM[rr] = *reinterpret_cast<const uint4*>(
          &sA[((ry + rr) * W + x0) * NW + slice * 4]);
      aL[rr] = (x0 > 0)
                   ? *reinterpret_cast<const uint4*>(
                         &sA[((ry + rr) * W + x0 - 1) * NW + slice * 4])
                   : make_uint4(0u, 0u, 0u, 0u);
    }
#pragma unroll
    for (int xi = 0; xi < XT; xi++) {
      int xc = x0 + xi;
      int cl = (xc > 0) ? 1 : 0;
      int cr = (xc < W - 1) ? 1 : 0;
#pragma unroll
      for (int rr = 0; rr < 3; rr++)
        aR[rr] = cr ? *reinterpret_cast<const uint4*>(
                          &sA[((ry + rr) * W + xc + 1) * NW + slice * 4])
                    : make_uint4(0u, 0u, 0u, 0u);
      int cnt = 0;
#pragma unroll
      for (int rr = 0; rr < 3; rr++) {
        int rvalid = (rr == 0) ? rv0 : ((rr == 2) ? rv2 : 1);
        if (rvalid) {
          if (cl) cnt += popc4(aL[rr], wt[rr * 3 + 0]);
          cnt += popc4(aM[rr], wt[rr * 3 + 1]);
          if (cr) cnt += popc4(aR[rr], wt[rr * 3 + 2]);
        }
      }
#pragma unroll
      for (int o = 1; o < SPLIT; o <<= 1)
        cnt += __shfl_xor_sync(0xffffffffu, cnt, o);
      int ncols = 1 + cl + cr;
      int val = nrows * ncols * 32 * NW - 2 * cnt;
      if (POOL) {
        if ((xi & 1) == 0) {
          tmpv = val;
        } else {
          int m2 = max(tmpv, val);
          if ((ry & 1) == 0) {
            pmax[xi >> 1] = m2;
          } else {
            int m = max(pmax[xi >> 1], m2);
            if (slice == 0)
              out[(((size_t)n * CO + co) * (H / 2) + (y >> 1)) * (W / 2) +
                  (xc >> 1)] = (short)m;
          }
        }
      } else {
        if (slice == 0)
          out[(((size_t)n * CO + co) * H + y) * W + xc] = (short)val;
      }
#pragma unroll
      for (int rr = 0; rr < 3; rr++) {
        aL[rr] = aM[rr];
        aM[rr] = aR[rr];
      }
    }
  }
}

// ------------- bn + hardtanh (final block output, fp64 path) ---------------
__global__ __launch_bounds__(256) void bn_ht_kernel(
    const short* __restrict__ in, const double* __restrict__ scale,
    const double* __restrict__ shift, float* __restrict__ out,
    int C, int HW, int total) {
  int idx = blockIdx.x * blockDim.x + threadIdx.x;
  if (idx >= total) return;
  int c = (idx / HW) % C;
  double z = (double)in[idx] * scale[c] + shift[c];
  z = fmin(1.0, fmax(-1.0, z));
  out[idx] = (float)z;
}

// ---------------- FC: [256,8192] @ [10,8192]^T + b (fp64 acc) --------------
__global__ __launch_bounds__(256) void fc_kernel(
    const float* __restrict__ h, const float* __restrict__ wfc,
    const float* __restrict__ bfc, float* __restrict__ out) {
  int gtid = blockIdx.x * blockDim.x + threadIdx.x;
  int warp = gtid >> 5;
  int lane = gtid & 31;
  if (warp >= 256 * 10) return;
  int n = warp / 10, k = warp % 10;
  const float* hp = h + (size_t)n * 8192;
  const float* wp = wfc + (size_t)k * 8192;
  double s = 0.0;
  for (int j = lane; j < 8192; j += 32) s += (double)hp[j] * (double)wp[j];
#pragma unroll
  for (int o = 16; o > 0; o >>= 1) s += __shfl_xor_sync(0xFFFFFFFFu, s, o);
  if (lane == 0) out[n * 10 + k] = (float)(s + (double)bfc[k]);
}

// ---------------------------------------------------------------------------
static inline int cdiv(int a, int b) { return (a + b - 1) / b; }

extern "C" void kernel_launch(void* const* d_in, const int* in_sizes, int n_in,
                              void* d_out, int out_size) {
  const float* x   = (const float*)d_in[0];
  const float* w0_ = (const float*)d_in[1];
  const float* g0  = (const float*)d_in[2];
  const float* b0  = (const float*)d_in[3];
  const float* wc1 = (const float*)d_in[4];
  const float* g1  = (const float*)d_in[5];
  const float* b1  = (const float*)d_in[6];
  const float* wc2 = (const float*)d_in[7];
  const float* g2  = (const float*)d_in[8];
  const float* b2  = (const float*)d_in[9];
  const float* wc3 = (const float*)d_in[10];
  const float* g3  = (const float*)d_in[11];
  const float* b3  = (const float*)d_in[12];
  const float* wc4 = (const float*)d_in[13];
  const float* g4  = (const float*)d_in[14];
  const float* b4  = (const float*)d_in[15];
  const float* wc5 = (const float*)d_in[16];
  const float* g5  = (const float*)d_in[17];
  const float* b5  = (const float*)d_in[18];
  const float* wfc = (const float*)d_in[19];
  const float* bfc = (const float*)d_in[20];
  float* out = (float*)d_out;

  float *A, *Cb;
  double *sc, *sf, *part;
  int *thr, *sgn;
  uint32_t *P, *Wp;
  cudaGetSymbolAddress((void**)&A, g_A);
  cudaGetSymbolAddress((void**)&Cb, g_C);
  cudaGetSymbolAddress((void**)&P, g_P);
  cudaGetSymbolAddress((void**)&Wp, g_Wp);
  cudaGetSymbolAddress((void**)&sc, g_scale);
  cudaGetSymbolAddress((void**)&sf, g_shift);
  cudaGetSymbolAddress((void**)&thr, g_ithr);
  cudaGetSymbolAddress((void**)&sgn, g_isgn);
  cudaGetSymbolAddress((void**)&part, g_part);
  short* As = (short*)A;
  short* Cs = (short*)Cb;

  const int N = 256;
  const int TB = 256;

  // ---- weight packing (input-only deps; front-loaded) ----
  packw_kernel<<<cdiv(4608, TB), TB>>>(wc1, Wp + 0,     128, 4608);
  packw_kernel<<<cdiv(9216, TB), TB>>>(wc2, Wp + 4608,  128, 9216);
  packw_kernel<<<cdiv(18432, TB), TB>>>(wc3, Wp + 13824, 256, 18432);
  packw_kernel<<<cdiv(36864, TB), TB>>>(wc4, Wp + 32256, 256, 36864);
  packw_kernel<<<cdiv(73728, TB), TB>>>(wc5, Wp + 69120, 512, 73728);

  // ---- conv0 + bn0 (fp64, deterministic 2-stage) ----
  conv0_kernel<<<N * 32, TB>>>(x, w0_, A);
  stats0_partial<<<dim3(128, 8), TB>>>(A, part, 128, 1024, 32);
  stats0_fin<<<1, 128>>>(part, g0, b0, sc, sf, 128, 8, 256.0 * 1024.0);
  pack0_kernel<<<N * 1024 * 4 / TB, TB>>>(A, sc, sf, P, 128, 1024, 4);

  // ---- block1: bconv 128->128 @32 +pool -> Cs ----
  bconv2_kernel<128, 128, 32, 32, 4, 1, 4, 16, true>
      <<<N * 8, TB>>>(P, Wp + 0, Cs);
  stats_int_kernel<<<128, TB>>>(Cs, g1, b1, sc, sf, thr, sgn, N, 128, 256);
  pack_int_kernel<<<N * 256 * 4 / TB, TB>>>(Cs, thr, sgn, P, 128, 256, 4);

  // ---- block2: bconv 128->256 @16 -> As ----
  bconv2_kernel<256, 256, 16, 16, 4, 1, 4, 16, false>
      <<<N * 4, TB>>>(P, Wp + 4608, As);
  stats_int_kernel<<<256, TB>>>(As, g2, b2, sc, sf, thr, sgn, N, 256, 256);
  pack_int_kernel<<<N * 256 * 8 / TB, TB>>>(As, thr, sgn, P, 256, 256, 8);

  // ---- block3: bconv 256->256 @16 +pool -> Cs ----
  bconv2_kernel<256, 128, 16, 16, 8, 2, 4, 16, true>
      <<<N * 8, TB>>>(P, Wp + 13824, Cs);
  stats_int_kernel<<<256, TB>>>(Cs, g3, b3, sc, sf, thr, sgn, N, 256, 64);
  pack_int_kernel<<<N * 64 * 8 / TB, TB>>>(Cs, thr, sgn, P, 256, 64, 8);

  // ---- block4: bconv 256->512 @8 -> As ----
  bconv2_kernel<512, 128, 8, 8, 8, 2, 4, 8, false>
      <<<N * 8, TB>>>(P, Wp + 32256, As);
  stats_int_kernel<<<512, TB>>>(As, g4, b4, sc, sf, thr, sgn, N, 512, 64);
  pack_int_kernel<<<N * 64 * 16 / TB, TB>>>(As, thr, sgn, P, 512, 64, 16);

  // ---- block5: bconv 512->512 @8 +pool -> Cs ----
  bconv2_kernel<512, 64, 8, 8, 16, 4, 4, 8, true>
      <<<N * 16, TB>>>(P, Wp + 69120, Cs);
  stats_int_kernel<<<512, TB>>>(Cs, g5, b5, sc, sf, thr, sgn, N, 512, 16);

  // ---- bn5 + hardtanh -> A, then FC ----
  {
    int to = N * 512 * 16;
    bn_ht_kernel<<<cdiv(to, TB), TB>>>(Cs, sc, sf, A, 512, 16, to);
    fc_kernel<<<cdiv(N * 10 * 32, TB), TB>>>(A, wfc, bfc, out);
  }
}

// round 5
// speedup vs baseline: 1.8973x; 1.2623x over previous
#include <cuda_runtime.h>
#include <cstdint>
#include <math.h>

// ---------------------------------------------------------------------------
// VGG-small 1w1a forward, batch 256.
//  conv0 fp32 tiled -> compensated-fp32 stats0 -> exact fp32 threshold pack0
//  -> [bconv(int16, fused pool) -> int64 stats -> int pack] x5 -> bn+ht -> fc
// ---------------------------------------------------------------------------

__device__ __align__(16) float    g_A[33554432];   // also reused as int16
__device__ __align__(16) float    g_C[8388608];    // also reused as int16
__device__ __align__(16) uint32_t g_P[1048576];    // packed activations
__device__ __align__(16) uint32_t g_Wp[147456];    // packed weights (all 5)
__device__ double g_scale[512];
__device__ double g_shift[512];
__device__ float  g_fsc[512];
__device__ float  g_fsf[512];
__device__ float  g_fthr[512];
__device__ int    g_fsgn[512];
__device__ int    g_ithr[512];
__device__ int    g_isgn[512];
__device__ double g_part[4096];

// ---------------- compensated fp32 helpers (contraction-proof) -------------
__device__ __forceinline__ void two_sum(float& s, float& c, float v) {
  float t = __fadd_rn(s, v);
  float z = __fsub_rn(t, s);
  float e = __fadd_rn(__fsub_rn(s, __fsub_rn(t, z)), __fsub_rn(v, z));
  s = t;
  c = __fadd_rn(c, e);
}

// ---------------- conv0: fp32 3->128, 32x32, pad 1 -------------------------
__global__ __launch_bounds__(256) void conv0_kernel(
    const float* __restrict__ x, const float* __restrict__ w,
    float* __restrict__ out) {
  __shared__ float sW[128 * 27];
  __shared__ float sX[3][3][34];
  int bx = blockIdx.x;
  int y = bx & 31, n = bx >> 5;
  int tid = threadIdx.x;
  for (int i = tid; i < 3456; i += 256) sW[i] = w[i];
  for (int i = tid; i < 3 * 3 * 34; i += 256) {
    int col = i % 34;
    int r = (i / 34) % 3;
    int ci = i / (34 * 3);
    int gy = y - 1 + r, gx = col - 1;
    float v = 0.f;
    if (gy >= 0 && gy < 32 && gx >= 0 && gx < 32)
      v = x[((n * 3 + ci) * 32 + gy) * 32 + gx];
    sX[ci][r][col] = v;
  }
  __syncthreads();
  int co = tid >> 1, xh = tid & 1, x0 = xh * 16;
  float wr[27];
#pragma unroll
  for (int ky = 0; ky < 3; ky++)
#pragma unroll
    for (int kx = 0; kx < 3; kx++)
#pragma unroll
      for (int ci = 0; ci < 3; ci++)
        wr[(ky * 3 + kx) * 3 + ci] = sW[((co * 3 + ci) * 3 + ky) * 3 + kx];
  float a[3][3][3];
#pragma unroll
  for (int r = 0; r < 3; r++)
#pragma unroll
    for (int ci = 0; ci < 3; ci++) {
      a[r][0][ci] = sX[ci][r][x0];
      a[r][1][ci] = sX[ci][r][x0 + 1];
    }
  float* obase = out + (((size_t)n * 128 + co) * 32 + y) * 32;
#pragma unroll
  for (int xi = 0; xi < 16; xi++) {
    int xc = x0 + xi;
#pragma unroll
    for (int r = 0; r < 3; r++)
#pragma unroll
      for (int ci = 0; ci < 3; ci++) a[r][2][ci] = sX[ci][r][xc + 2];
    float acc = 0.f;
#pragma unroll
    for (int ky = 0; ky < 3; ky++)
#pragma unroll
      for (int kx = 0; kx < 3; kx++)
#pragma unroll
        for (int ci = 0; ci < 3; ci++)
          acc = fmaf(a[ky][kx][ci], wr[(ky * 3 + kx) * 3 + ci], acc);
    obase[xc] = acc;
#pragma unroll
    for (int r = 0; r < 3; r++)
#pragma unroll
      for (int ci = 0; ci < 3; ci++) {
        a[r][0][ci] = a[r][1][ci];
        a[r][1][ci] = a[r][2][ci];
      }
  }
}

// -------- layer0 stats: compensated fp32, fp64 cross-thread reduce ---------
__global__ __launch_bounds__(256) void stats0_partial(
    const float* __restrict__ x, double* __restrict__ part,
    int C, int HW, int CH) {
  int c = blockIdx.x, ch = blockIdx.y;
  float s = 0.f, cs = 0.f, ss = 0.f, css = 0.f;
  for (int n = ch * CH; n < (ch + 1) * CH; n++) {
    const float* p = x + ((size_t)n * C + c) * HW;
    for (int i = threadIdx.x; i < HW; i += 256) {
      float v = p[i];
      two_sum(s, cs, v);
      float v2 = __fmul_rn(v, v);
      float e2 = __fmaf_rn(v, v, -v2);      // exact square residual
      two_sum(ss, css, v2);
      css = __fadd_rn(css, e2);
    }
  }
  __shared__ double sh1[256], sh2[256];
  sh1[threadIdx.x] = (double)s + (double)cs;
  sh2[threadIdx.x] = (double)ss + (double)css;
  __syncthreads();
  for (int o = 128; o > 0; o >>= 1) {
    if (threadIdx.x < o) {
      sh1[threadIdx.x] += sh1[threadIdx.x + o];
      sh2[threadIdx.x] += sh2[threadIdx.x + o];
    }
    __syncthreads();
  }
  if (threadIdx.x == 0) {
    part[c * gridDim.y + ch] = sh1[0];
    part[C * gridDim.y + c * gridDim.y + ch] = sh2[0];
  }
}

// ------- finalize stats0 + exact fp32 decision boundary per channel --------
__global__ void stats0_fin(const double* __restrict__ part,
                           const float* __restrict__ g,
                           const float* __restrict__ b,
                           float* __restrict__ fthr, int* __restrict__ fsgn,
                           int C, int CHUNKS, double cnt) {
  int c = blockIdx.x * blockDim.x + threadIdx.x;
  if (c >= C) return;
  double S = 0.0, SS = 0.0;
  for (int ch = 0; ch < CHUNKS; ch++) {
    S += part[c * CHUNKS + ch];
    SS += part[C * CHUNKS + c * CHUNKS + ch];
  }
  double mean = S / cnt;
  double var = SS / cnt - mean * mean;
  double sc = (double)g[c] * rsqrt(var + 1e-5);
  double sf = (double)b[c] - mean * sc;
  // predicate Q(v) = fma(v, sc, sf) >= 0, monotone in v
  if (sc > 0.0) {
    float v = (float)(-sf / sc);
    if (!isfinite(v)) v = 0.f;
    if (fma((double)v, sc, sf) >= 0.0) {
      for (int it = 0; it < 64; it++) {
        float d = nextafterf(v, -INFINITY);
        if (fma((double)d, sc, sf) >= 0.0) v = d; else break;
      }
    } else {
      for (int it = 0; it < 64; it++) {
        v = nextafterf(v, INFINITY);
        if (fma((double)v, sc, sf) >= 0.0) break;
      }
    }
    fthr[c] = v;          // bit = (x >= v)
    fsgn[c] = 1;
  } else if (sc < 0.0) {
    float v = (float)(-sf / sc);
    if (!isfinite(v)) v = 0.f;
    if (fma((double)v, sc, sf) >= 0.0) {
      for (int it = 0; it < 64; it++) {
        float d = nextafterf(v, INFINITY);
        if (fma((double)d, sc, sf) >= 0.0) v = d; else break;
      }
    } else {
      for (int it = 0; it < 64; it++) {
        v = nextafterf(v, -INFINITY);
        if (fma((double)v, sc, sf) >= 0.0) break;
      }
    }
    fthr[c] = v;          // bit = (x <= v)
    fsgn[c] = 0;
  } else {
    fthr[c] = (sf >= 0.0) ? -INFINITY : INFINITY;
    fsgn[c] = 1;
  }
}

// -------- layer0 pack: pure fp32 compare against exact boundary ------------
__global__ __launch_bounds__(256) void pack0_kernel(
    const float* __restrict__ x, const float* __restrict__ fthr,
    const int* __restrict__ fsgn, uint32_t* __restrict__ apk,
    int C, int HW, int NW) {
  int gt = blockIdx.x * 256 + threadIdx.x;
  int lane = gt & 31;
  int gw = gt >> 5;
  int wrd = gw % NW;
  int chunk = gw / NW;
  int pixel = chunk * 32 + lane;
  int n = pixel / HW, hw = pixel % HW;
  const float* base = x + ((size_t)n * C + wrd * 32) * HW + hw;
  const float* tp = fthr + wrd * 32;
  const int* sp = fsgn + wrd * 32;
  uint32_t bits = 0;
#pragma unroll 8
  for (int k = 0; k < 32; k++) {
    float v = base[(size_t)k * HW];
    bool bit = sp[k] ? (v >= tp[k]) : (v <= tp[k]);
    bits |= (bit ? 1u : 0u) << k;
  }
  apk[(size_t)pixel * NW + wrd] = bits;
}

// -------- binary-layer stats: exact int64 accumulation ---------------------
__global__ __launch_bounds__(256) void stats_int_kernel(
    const short* __restrict__ x, const float* __restrict__ g,
    const float* __restrict__ b, double* __restrict__ scale,
    double* __restrict__ shift, float* __restrict__ fsc,
    float* __restrict__ fsf, int* __restrict__ thr, int* __restrict__ sgn,
    int N, int C, int HW) {
  int c = blockIdx.x;
  long long s = 0, ss = 0;
  for (int n = 0; n < N; n++) {
    const short* p = x + ((size_t)n * C + c) * HW;
    for (int i = threadIdx.x; i < HW; i += 256) {
      int v = p[i];
      s += v;
      ss += (long long)(v * v);
    }
  }
  __shared__ long long sh1[256], sh2[256];
  sh1[threadIdx.x] = s;
  sh2[threadIdx.x] = ss;
  __syncthreads();
  for (int o = 128; o > 0; o >>= 1) {
    if (threadIdx.x < o) {
      sh1[threadIdx.x] += sh1[threadIdx.x + o];
      sh2[threadIdx.x] += sh2[threadIdx.x + o];
    }
    __syncthreads();
  }
  if (threadIdx.x == 0) {
    double cnt = (double)N * (double)HW;
    double mean = (double)sh1[0] / cnt;
    double var = (double)sh2[0] / cnt - mean * mean;
    double sc = (double)g[c] * rsqrt(var + 1e-5);
    double sf = (double)b[c] - mean * sc;
    scale[c] = sc;
    shift[c] = sf;
    fsc[c] = (float)sc;
    fsf[c] = (float)sf;
    double T = -sf / sc;
    if (sc > 0.0) {
      thr[c] = (int)ceil(T);
      sgn[c] = 1;
    } else {
      thr[c] = (int)floor(T);
      sgn[c] = 0;
    }
  }
}

// -------- binary-layer pack: pure integer predicate ------------------------
__global__ __launch_bounds__(256) void pack_int_kernel(
    const short* __restrict__ x, const int* __restrict__ thr,
    const int* __restrict__ sgn, uint32_t* __restrict__ apk,
    int C, int HW, int NW) {
  int gt = blockIdx.x * 256 + threadIdx.x;
  int lane = gt & 31;
  int gw = gt >> 5;
  int wrd = gw % NW;
  int chunk = gw / NW;
  int pixel = chunk * 32 + lane;
  int n = pixel / HW, hw = pixel % HW;
  const short* base = x + ((size_t)n * C + wrd * 32) * HW + hw;
  const int* tp = thr + wrd * 32;
  const int* sp = sgn + wrd * 32;
  uint32_t bits = 0;
#pragma unroll 8
  for (int k = 0; k < 32; k++) {
    int v = base[(size_t)k * HW];
    bool bit = sp[k] ? (v >= tp[k]) : (v <= tp[k]);
    bits |= (bit ? 1u : 0u) << k;
  }
  apk[(size_t)pixel * NW + wrd] = bits;
}

// ------------- all weights -> bitpack, single launch -----------------------
__global__ __launch_bounds__(256) void packw_all_kernel(
    const float* __restrict__ w1, const float* __restrict__ w2,
    const float* __restrict__ w3, const float* __restrict__ w4,
    const float* __restrict__ w5, uint32_t* __restrict__ wpk) {
  int idx = blockIdx.x * blockDim.x + threadIdx.x;
  if (idx >= 142848) return;
  const float* w;
  int Ci, local;
  if (idx < 4608) { w = w1; Ci = 128; local = idx; }
  else if (idx < 13824) { w = w2; Ci = 128; local = idx - 4608; }
  else if (idx < 32256) { w = w3; Ci = 256; local = idx - 13824; }
  else if (idx < 69120) { w = w4; Ci = 256; local = idx - 32256; }
  else { w = w5; Ci = 512; local = idx - 69120; }
  int NW = Ci >> 5;
  int wrd = local % NW;
  int t = local / NW;
  int tap = t % 9;
  int co = t / 9;
  uint32_t bits = 0;
#pragma unroll 8
  for (int k = 0; k < 32; k++) {
    float v = w[(co * Ci + (wrd * 32 + k)) * 9 + tap];
    bits |= (v >= 0.f ? 1u : 0u) << k;
  }
  wpk[idx] = bits;
}

// ---------------- binary conv 3x3 pad 1 (+ fused maxpool), int16 out -------
__device__ __forceinline__ int popc4(uint4 a, uint4 b) {
  return __popc(a.x ^ b.x) + __popc(a.y ^ b.y) +
         __popc(a.z ^ b.z) + __popc(a.w ^ b.w);
}

template <int CO, int CO_G, int H, int W, int NW, int SPLIT, int YT, int XT,
          bool POOL>
__global__ __launch_bounds__(CO_G* SPLIT*(W / XT)) void bconv2_kernel(
    const uint32_t* __restrict__ apk, const uint32_t* __restrict__ wpk,
    short* __restrict__ out) {
  constexpr int NTH = CO_G * SPLIT * (W / XT);
  constexpr int CGRP = CO / CO_G;
  __shared__ uint32_t sW[CO_G * 9 * NW];
  __shared__ uint32_t sA[(YT + 2) * W * NW];
  int bx = blockIdx.x;
  int cg = bx % CGRP;
  int yg = (bx / CGRP) % (H / YT);
  int n = bx / (CGRP * (H / YT));
  int tid = threadIdx.x;
  const uint4* wsrc =
      reinterpret_cast<const uint4*>(wpk + (size_t)cg * CO_G * 9 * NW);
  for (int i = tid; i < CO_G * 9 * NW / 4; i += NTH)
    reinterpret_cast<uint4*>(sW)[i] = wsrc[i];
  int ybase = yg * YT;
  constexpr int RW4 = W * NW / 4;
  for (int i = tid; i < (YT + 2) * RW4; i += NTH) {
    int r = i / RW4;
    int gy = ybase - 1 + r;
    uint4 v = make_uint4(0u, 0u, 0u, 0u);
    if (gy >= 0 && gy < H)
      v = reinterpret_cast<const uint4*>(
          apk + ((size_t)(n * H + gy) * W) * NW)[i % RW4];
    reinterpret_cast<uint4*>(sA)[i] = v;
  }
  __syncthreads();
  int slice = tid % SPLIT;
  int t2 = tid / SPLIT;
  int xg = t2 % (W / XT);
  int co_l = t2 / (W / XT);
  int x0 = xg * XT;
  uint4 wt[9];
#pragma unroll
  for (int t = 0; t < 9; t++)
    wt[t] = *reinterpret_cast<const uint4*>(
        &sW[(co_l * 9 + t) * NW + slice * 4]);
  int co = cg * CO_G + co_l;
  int pmax[XT / 2];
  int tmpv = 0;
#pragma unroll
  for (int ry = 0; ry < YT; ry++) {
    int y = ybase + ry;
    int rv0 = (y > 0) ? 1 : 0;
    int rv2 = (y < H - 1) ? 1 : 0;
    int nrows = 1 + rv0 + rv2;
    uint4 aL[3], aM[3], aR[3];
#pragma unroll
    for (int rr = 0; rr < 3; rr++) {
      aM[rr] = *reinterpret_cast<const uint4*>(
          &sA[((ry + rr) * W + x0) * NW + slice * 4]);
      aL[rr] = (x0 > 0)
                   ? *reinterpret_cast<const uint4*>(
                         &sA[((ry + rr) * W + x0 - 1) * NW + slice * 4])
                   : make_uint4(0u, 0u, 0u, 0u);
    }
#pragma unroll
    for (int xi = 0; xi < XT; xi++) {
      int xc = x0 + xi;
      int cl = (xc > 0) ? 1 : 0;
      int cr = (xc < W - 1) ? 1 : 0;
#pragma unroll
      for (int rr = 0; rr < 3; rr++)
        aR[rr] = cr ? *reinterpret_cast<const uint4*>(
                          &sA[((ry + rr) * W + xc + 1) * NW + slice * 4])
                    : make_uint4(0u, 0u, 0u, 0u);
      int cnt = 0;
#pragma unroll
      for (int rr = 0; rr < 3; rr++) {
        int rvalid = (rr == 0) ? rv0 : ((rr == 2) ? rv2 : 1);
        if (rvalid) {
          if (cl) cnt += popc4(aL[rr], wt[rr * 3 + 0]);
          cnt += popc4(aM[rr], wt[rr * 3 + 1]);
          if (cr) cnt += popc4(aR[rr], wt[rr * 3 + 2]);
        }
      }
#pragma unroll
      for (int o = 1; o < SPLIT; o <<= 1)
        cnt += __shfl_xor_sync(0xffffffffu, cnt, o);
      int ncols = 1 + cl + cr;
      int val = nrows * ncols * 32 * NW - 2 * cnt;
      if (POOL) {
        if ((xi & 1) == 0) {
          tmpv = val;
        } else {
          int m2 = max(tmpv, val);
          if ((ry & 1) == 0) {
            pmax[xi >> 1] = m2;
          } else {
            int m = max(pmax[xi >> 1], m2);
            if (slice == 0)
              out[(((size_t)n * CO + co) * (H / 2) + (y >> 1)) * (W / 2) +
                  (xc >> 1)] = (short)m;
          }
        }
      } else {
        if (slice == 0)
          out[(((size_t)n * CO + co) * H + y) * W + xc] = (short)val;
      }
#pragma unroll
      for (int rr = 0; rr < 3; rr++) {
        aL[rr] = aM[rr];
        aM[rr] = aR[rr];
      }
    }
  }
}

// ------------- bn + hardtanh (fp32: continuous path, no thresholds) --------
__global__ __launch_bounds__(256) void bn_ht_kernel(
    const short* __restrict__ in, const float* __restrict__ fsc,
    const float* __restrict__ fsf, float* __restrict__ out,
    int C, int HW, int total) {
  int idx = blockIdx.x * blockDim.x + threadIdx.x;
  if (idx >= total) return;
  int c = (idx / HW) % C;
  float z = fmaf((float)in[idx], fsc[c], fsf[c]);
  out[idx] = fminf(1.f, fmaxf(-1.f, z));
}

// ----- FC: [256,8192] @ [10,8192]^T + b (TwoProd+Neumaier fp32) ------------
__global__ __launch_bounds__(256) void fc_kernel(
    const float* __restrict__ h, const float* __restrict__ wfc,
    const float* __restrict__ bfc, float* __restrict__ out) {
  int gtid = blockIdx.x * blockDim.x + threadIdx.x;
  int warp = gtid >> 5;
  int lane = gtid & 31;
  if (warp >= 256 * 10) return;
  int n = warp / 10, k = warp % 10;
  const float* hp = h + (size_t)n * 8192;
  const float* wp = wfc + (size_t)k * 8192;
  float s = 0.f, c = 0.f;
  for (int j = lane; j < 8192; j += 32) {
    float a = hp[j], b = wp[j];
    float p = __fmul_rn(a, b);
    float e = __fmaf_rn(a, b, -p);       // exact product residual
    two_sum(s, c, p);
    c = __fadd_rn(c, e);
  }
  double d = (double)s + (double)c;
#pragma unroll
  for (int o = 16; o > 0; o >>= 1) d += __shfl_xor_sync(0xFFFFFFFFu, d, o);
  if (lane == 0) out[n * 10 + k] = (float)(d + (double)bfc[k]);
}

// ---------------------------------------------------------------------------
static inline int cdiv(int a, int b) { return (a + b - 1) / b; }

extern "C" void kernel_launch(void* const* d_in, const int* in_sizes, int n_in,
                              void* d_out, int out_size) {
  const float* x   = (const float*)d_in[0];
  const float* w0_ = (const float*)d_in[1];
  const float* g0  = (const float*)d_in[2];
  const float* b0  = (const float*)d_in[3];
  const float* wc1 = (const float*)d_in[4];
  const float* g1  = (const float*)d_in[5];
  const float* b1  = (const float*)d_in[6];
  const float* wc2 = (const float*)d_in[7];
  const float* g2  = (const float*)d_in[8];
  const float* b2  = (const float*)d_in[9];
  const float* wc3 = (const float*)d_in[10];
  const float* g3  = (const float*)d_in[11];
  const float* b3  = (const float*)d_in[12];
  const float* wc4 = (const float*)d_in[13];
  const float* g4  = (const float*)d_in[14];
  const float* b4  = (const float*)d_in[15];
  const float* wc5 = (const float*)d_in[16];
  const float* g5  = (const float*)d_in[17];
  const float* b5  = (const float*)d_in[18];
  const float* wfc = (const float*)d_in[19];
  const float* bfc = (const float*)d_in[20];
  float* out = (float*)d_out;

  float *A, *Cb, *fsc, *fsf, *fthr;
  double *sc, *sf, *part;
  int *thr, *sgn, *fsgn;
  uint32_t *P, *Wp;
  cudaGetSymbolAddress((void**)&A, g_A);
  cudaGetSymbolAddress((void**)&Cb, g_C);
  cudaGetSymbolAddress((void**)&P, g_P);
  cudaGetSymbolAddress((void**)&Wp, g_Wp);
  cudaGetSymbolAddress((void**)&sc, g_scale);
  cudaGetSymbolAddress((void**)&sf, g_shift);
  cudaGetSymbolAddress((void**)&fsc, g_fsc);
  cudaGetSymbolAddress((void**)&fsf, g_fsf);
  cudaGetSymbolAddress((void**)&fthr, g_fthr);
  cudaGetSymbolAddress((void**)&fsgn, g_fsgn);
  cudaGetSymbolAddress((void**)&thr, g_ithr);
  cudaGetSymbolAddress((void**)&sgn, g_isgn);
  cudaGetSymbolAddress((void**)&part, g_part);
  short* As = (short*)A;
  short* Cs = (short*)Cb;

  const int N = 256;
  const int TB = 256;

  // launch 0: all weight packing (input-only deps)
  packw_all_kernel<<<cdiv(142848, TB), TB>>>(wc1, wc2, wc3, wc4, wc5, Wp);

  // ---- conv0 + bn0 ----
  conv0_kernel<<<N * 32, TB>>>(x, w0_, A);                       // launch 1
  stats0_partial<<<dim3(128, 8), TB>>>(A, part, 128, 1024, 32);  // launch 2
  stats0_fin<<<1, 128>>>(part, g0, b0, fthr, fsgn, 128, 8,       // launch 3
                         256.0 * 1024.0);
  pack0_kernel<<<N * 1024 * 4 / TB, TB>>>(A, fthr, fsgn, P, 128, 1024,
                                          4);                    // launch 4

  // ---- block1: bconv 128->128 @32 +pool -> Cs ----   (launch 5: profiled)
  bconv2_kernel<128, 128, 32, 32, 4, 1, 4, 16, true>
      <<<N * 8, TB>>>(P, Wp + 0, Cs);
  stats_int_kernel<<<128, TB>>>(Cs, g1, b1, sc, sf, fsc, fsf, thr, sgn, N,
                                128, 256);
  pack_int_kernel<<<N * 256 * 4 / TB, TB>>>(Cs, thr, sgn, P, 128, 256, 4);

  // ---- block2: bconv 128->256 @16 -> As ----
  bconv2_kernel<256, 256, 16, 16, 4, 1, 4, 16, false>
      <<<N * 4, TB>>>(P, Wp + 4608, As);
  stats_int_kernel<<<256, TB>>>(As, g2, b2, sc, sf, fsc, fsf, thr, sgn, N,
                                256, 256);
  pack_int_kernel<<<N * 256 * 8 / TB, TB>>>(As, thr, sgn, P, 256, 256, 8);

  // ---- block3: bconv 256->256 @16 +pool -> Cs ----
  bconv2_kernel<256, 128, 16, 16, 8, 2, 4, 16, true>
      <<<N * 8, TB>>>(P, Wp + 13824, Cs);
  stats_int_kernel<<<256, TB>>>(Cs, g3, b3, sc, sf, fsc, fsf, thr, sgn, N,
                                256, 64);
  pack_int_kernel<<<N * 64 * 8 / TB, TB>>>(Cs, thr, sgn, P, 256, 64, 8);

  // ---- block4: bconv 256->512 @8 -> As ----
  bconv2_kernel<512, 128, 8, 8, 8, 2, 4, 8, false>
      <<<N * 8, TB>>>(P, Wp + 32256, As);
  stats_int_kernel<<<512, TB>>>(As, g4, b4, sc, sf, fsc, fsf, thr, sgn, N,
                                512, 64);
  pack_int_kernel<<<N * 64 * 16 / TB, TB>>>(As, thr, sgn, P, 512, 64, 16);

  // ---- block5: bconv 512->512 @8 +pool -> Cs ----
  bconv2_kernel<512, 64, 8, 8, 16, 4, 4, 8, true>
      <<<N * 16, TB>>>(P, Wp + 69120, Cs);
  stats_int_kernel<<<512, TB>>>(Cs, g5, b5, sc, sf, fsc, fsf, thr, sgn, N,
                                512, 16);

  // ---- bn5 + hardtanh -> A, then FC ----
  {
    int to = N * 512 * 16;
    bn_ht_kernel<<<cdiv(to, TB), TB>>>(Cs, fsc, fsf, A, 512, 16, to);
    fc_kernel<<<cdiv(N * 10 * 32, TB), TB>>>(A, wfc, bfc, out);
  }
}